// round 15
// baseline (speedup 1.0000x reference)
#include <cuda_runtime.h>
#include <cuda_bf16.h>
#include <cuda_fp8.h>
#include <cstdint>

#define B_    8
#define L_    512
#define H_    12
#define D_    64
#define HID   768
#define OUTD  1536
#define MROWS 4096          // B_*L_
#define BHN   96            // B_*H_

#define NA4   (MROWS * HID / 4)     // 786432 float4 units of A
#define NAQ   (NA4 / 4)             // 196608
#define NROPE (L_ * 32)             //  16384

// Scratch (device globals — no runtime allocation allowed)
__device__ unsigned char g_a8[MROWS * HID];     // inputs e4m3 [4096 x 768]
__device__ unsigned char g_wt8[OUTD * HID];     // W^T e4m3 [1536 x 768] K-major
__device__ unsigned char g_q8[BHN * L_ * D_];   // q, (bh, l, d) e4m3
__device__ unsigned char g_k8[BHN * L_ * D_];   // k, (bh, l, d) e4m3
__device__ float         g_sin[NROPE];
__device__ float         g_cos[NROPE];

// ---------------------------------------------------------------------------
// PTX helpers
// ---------------------------------------------------------------------------
static __device__ __forceinline__ uint32_t smem_u32(const void* p) {
    uint32_t a;
    asm("{ .reg .u64 t; cvta.to.shared.u64 t, %1; cvt.u32.u64 %0, t; }" : "=r"(a) : "l"(p));
    return a;
}
static __device__ __forceinline__ void cp_async16_s(uint32_t saddr, const void* g) {
    asm volatile("cp.async.cg.shared.global [%0], [%1], 16;\n" :: "r"(saddr), "l"(g));
}
static __device__ __forceinline__ void cp_commit() {
    asm volatile("cp.async.commit_group;\n" ::: "memory");
}
static __device__ __forceinline__ void ldsm_x4(uint32_t* r, uint32_t addr) {
    asm volatile("ldmatrix.sync.aligned.m8n8.x4.shared.b16 {%0,%1,%2,%3}, [%4];"
                 : "=r"(r[0]), "=r"(r[1]), "=r"(r[2]), "=r"(r[3]) : "r"(addr));
}
// fp8 e4m3 MMA: D(16x8 f32) += A(16x32) * B(8x32)^T
static __device__ __forceinline__ void mma16832(float* d, const uint32_t* a, const uint32_t* b) {
    asm volatile(
        "mma.sync.aligned.m16n8k32.row.col.f32.e4m3.e4m3.f32 "
        "{%0,%1,%2,%3}, {%4,%5,%6,%7}, {%8,%9}, {%0,%1,%2,%3};"
        : "+f"(d[0]), "+f"(d[1]), "+f"(d[2]), "+f"(d[3])
        : "r"(a[0]), "r"(a[1]), "r"(a[2]), "r"(a[3]), "r"(b[0]), "r"(b[1]));
}
static __device__ __forceinline__ unsigned short f2_to_e4m3x2(float x, float y) {
    return (unsigned short)__nv_cvt_float2_to_fp8x2(make_float2(x, y), __NV_SATFINITE, __NV_E4M3);
}

// ---------------------------------------------------------------------------
// Kernel 0: convert inputs to e4m3 + RoPE tables.
// ---------------------------------------------------------------------------
static __device__ __forceinline__ void conv_a(const float* __restrict__ A, int j) {
    float4 v = reinterpret_cast<const float4*>(A)[j];
    uint32_t lo = f2_to_e4m3x2(v.x, v.y);
    uint32_t hi = f2_to_e4m3x2(v.z, v.w);
    reinterpret_cast<uint32_t*>(g_a8)[j] = lo | (hi << 16);
}

__global__ __launch_bounds__(256) void prep_kernel(const float* __restrict__ A) {
    int idx = blockIdx.x * 256 + threadIdx.x;
    if (idx < NAQ) {
        conv_a(A, idx);
        conv_a(A, idx + NAQ);
        conv_a(A, idx + 2 * NAQ);
        conv_a(A, idx + 3 * NAQ);
    } else if (idx < NAQ + NROPE) {
        int t = idx - NAQ;
        int l = t >> 5;
        int i = t & 31;
        float invf = exp2f((float)i * -0.41524101186092027f);
        float s, c;
        sincosf((float)l * invf, &s, &c);
        g_sin[t] = s;
        g_cos[t] = c;
    }
}

// ---------------------------------------------------------------------------
// Kernel 0b: W [768 x 1536] f32 -> g_wt8 [1536 x 768] e4m3 (tiled transpose)
// ---------------------------------------------------------------------------
__global__ __launch_bounds__(256) void wtrans_kernel(const float* __restrict__ W) {
    __shared__ float t[32][33];
    int n0 = blockIdx.x * 32, k0 = blockIdx.y * 32;
    int tx = threadIdx.x & 31, ty = threadIdx.x >> 5;   // 32x8
    #pragma unroll
    for (int i = 0; i < 4; i++)
        t[ty + i*8][tx] = W[(size_t)(k0 + ty + i*8) * OUTD + n0 + tx];
    __syncthreads();
    #pragma unroll
    for (int i = 0; i < 4; i++)
        g_wt8[(size_t)(n0 + ty + i*8) * HID + k0 + tx] =
            (unsigned char)__nv_cvt_float_to_fp8(t[tx][ty + i*8], __NV_SATFINITE, __NV_E4M3);
}

// ---------------------------------------------------------------------------
// Kernel 1: x = inputs @ W via fp8 mma.sync, bias+RoPE in registers, e4m3 out.
// Block 128m x 128n (one head), 8 warps (2x4), warp 64m x 32n.
// BK=128, 2-stage cp.async pipeline. Output staged in smem -> STG.128.
// ---------------------------------------------------------------------------
#define G1_ROWB   144                       // 128B fp8 data + 16B pad
#define G1_OPB    (128 * G1_ROWB)           // 18432 per operand
#define G1_STAGE  (2 * G1_OPB)              // 36864
#define G1_SMEM   (2 * G1_STAGE)            // 73728
#define ST_ROWB   144                       // staging row stride (conflict-free)

__global__ __launch_bounds__(256, 2) void gemm1_kernel(const float* __restrict__ bias) {
    extern __shared__ __align__(16) unsigned char dsm[];
    __shared__ float bias_s[128];

    const int tid  = threadIdx.x;
    const int lane = tid & 31;
    const int w    = tid >> 5;
    const int wm   = w >> 2;             // 0..1 (m offset 64)
    const int wn   = w & 3;              // 0..3 (n offset 32)
    const int h    = blockIdx.x;
    const int m0   = blockIdx.y * 128;
    const int n0   = h * 128;

    if (tid < 128) bias_s[tid] = __ldg(&bias[n0 + tid]);

    const uint32_t sbase = smem_u32(dsm);

    auto copy_stage = [&](int kt) {
        uint32_t base = sbase + (kt & 1) * G1_STAGE;
        int k0e = kt * 128;
        #pragma unroll
        for (int it = 0; it < 8; it++) {
            int idx = tid + it * 256;            // 0..2047
            int r = (idx >> 3) & 127;
            int c = idx & 7;                     // 16B chunk
            if (idx < 1024)
                cp_async16_s(base + r * G1_ROWB + c * 16,
                             &g_a8[(size_t)(m0 + r) * HID + k0e + c * 16]);
            else
                cp_async16_s(base + G1_OPB + r * G1_ROWB + c * 16,
                             &g_wt8[(size_t)(n0 + r) * HID + k0e + c * 16]);
        }
    };

    uint32_t a_off[4], b_off[2];
    #pragma unroll
    for (int mi = 0; mi < 4; mi++)
        a_off[mi] = (uint32_t)((wm*64 + mi*16 + (lane & 15)) * G1_ROWB + ((lane >> 4) * 16));
    #pragma unroll
    for (int p = 0; p < 2; p++)
        b_off[p] = (uint32_t)(G1_OPB + (wn*32 + p*16 + (lane & 15)) * G1_ROWB + ((lane >> 4) * 16));

    float acc[4][4][4];
    #pragma unroll
    for (int mi = 0; mi < 4; mi++)
        #pragma unroll
        for (int nj = 0; nj < 4; nj++)
            #pragma unroll
            for (int x = 0; x < 4; x++)
                acc[mi][nj][x] = 0.0f;

    copy_stage(0); cp_commit();

    const int NT = HID / 128;   // 6
    for (int kt = 0; kt < NT; kt++) {
        if (kt + 1 < NT) {
            copy_stage(kt + 1); cp_commit();
            asm volatile("cp.async.wait_group 1;" ::: "memory");
        } else {
            asm volatile("cp.async.wait_group 0;" ::: "memory");
        }
        __syncthreads();

        uint32_t stg = sbase + (kt & 1) * G1_STAGE;
        #pragma unroll
        for (int ks = 0; ks < 4; ks++) {         // four k32 steps per BK=128
            uint32_t koff = ks * 32;
            uint32_t a[4][4], bp[2][4];
            #pragma unroll
            for (int mi = 0; mi < 4; mi++)
                ldsm_x4(a[mi], stg + a_off[mi] + koff);
            #pragma unroll
            for (int p = 0; p < 2; p++)
                ldsm_x4(bp[p], stg + b_off[p] + koff);
            #pragma unroll
            for (int mi = 0; mi < 4; mi++)
                #pragma unroll
                for (int nj = 0; nj < 4; nj++) {
                    uint32_t bb[2] = { bp[nj >> 1][nj & 1], bp[nj >> 1][(nj & 1) + 2] };
                    mma16832(acc[mi][nj], a[mi], bb);
                }
        }
        __syncthreads();
    }

    // Epilogue: bias + RoPE in registers -> fp8x2 into smem staging
    // (row stride 144B => conflict-free STS.16), then coalesced STG.128.
    unsigned char* stage = dsm;             // 128 x 144 = 18432 bytes
    float bv[4][2];
    #pragma unroll
    for (int nj = 0; nj < 4; nj++) {
        int nl = wn*32 + nj*8 + (lane & 3) * 2;
        bv[nj][0] = bias_s[nl];
        bv[nj][1] = bias_s[nl + 1];
    }

    #pragma unroll
    for (int mi = 0; mi < 4; mi++) {
        #pragma unroll
        for (int rh = 0; rh < 2; rh++) {
            int row = wm*64 + mi*16 + (lane >> 2) + rh*8;    // 0..127
            int l = (m0 + row) & (L_ - 1);
            #pragma unroll
            for (int nj = 0; nj < 4; nj++) {
                float x1 = acc[mi][nj][rh*2 + 0] + bv[nj][0];
                float x2 = acc[mi][nj][rh*2 + 1] + bv[nj][1];
                int nl = wn*32 + nj*8 + (lane & 3) * 2;
                int i  = (nl & 63) >> 1;
                float s = g_sin[l * 32 + i];
                float c = g_cos[l * 32 + i];
                unsigned short pr = f2_to_e4m3x2(x1 * c - x2 * s, x1 * s + x2 * c);
                *reinterpret_cast<unsigned short*>(stage + row * ST_ROWB + nl) = pr;
            }
        }
    }
    __syncthreads();

    // 128 rows x 8 chunks of 16B = 1024 uint4; 4 per thread.
    #pragma unroll
    for (int it = 0; it < 4; it++) {
        int idx = tid + it * 256;           // 0..1023
        int row = idx >> 3;
        int c   = idx & 7;
        uint4 v = *reinterpret_cast<const uint4*>(stage + row * ST_ROWB + c * 16);
        int m_g = m0 + row;
        int l = m_g & (L_ - 1);
        int bidx = m_g >> 9;
        unsigned char* dst = (c < 4) ? g_q8 : g_k8;
        int d = (c & 3) * 16;
        *reinterpret_cast<uint4*>(&dst[((size_t)(bidx * H_ + h) * L_ + l) * D_ + d]) = v;
    }
}

// ---------------------------------------------------------------------------
// Kernel 2: logits = (q @ k^T)/8. Row-stripe blocks: grid (4, 96); each block
// owns 128 rows, loads q once, loops over 4 column tiles (fill fast-path for
// tn < tm). fp8 mma.sync, 8 warps (2x4), register float2 epilogue.
// ---------------------------------------------------------------------------
#define AT_ROWB 80    // 64 fp8 (64B) + 16B pad

__global__ __launch_bounds__(256, 2) void attn_kernel(const int* __restrict__ am,
                                                      float* __restrict__ out) {
    const int bh = blockIdx.y;
    const int tm = blockIdx.x;
    const int m0 = tm * 128;
    float* obase = out + (size_t)bh * L_ * L_;
    const float NEG = __int_as_float(0xFF7FFFFF);  // -FLT_MAX == finfo(f32).min
    const int tid  = threadIdx.x;
    const int b    = bh / H_;
    const int lane = tid & 31;
    const int w    = tid >> 5;
    const int wm   = w >> 2;     // 0..1
    const int wn   = w & 3;      // 0..3

    __shared__ __align__(16) unsigned char qmem[128 * AT_ROWB];
    __shared__ __align__(16) unsigned char kmem[128 * AT_ROWB];
    __shared__ unsigned char maskv[512];

    const int* amb = am + b * L_;
    if (tid < 256) {
        maskv[tid]       = (unsigned char)(amb[tid] != 0);
        maskv[tid + 256] = (unsigned char)(amb[tid + 256] != 0);
    }

    const unsigned char* qb = &g_q8[(size_t)bh * L_ * D_];
    const unsigned char* kb = &g_k8[(size_t)bh * L_ * D_];

    // load q tile once: 512 uint4, 2 per thread
    const uint32_t qbase = smem_u32(qmem);
    const uint32_t kbase = smem_u32(kmem);
    #pragma unroll
    for (int it = 0; it < 2; it++) {
        int idx = tid + it * 256;              // 0..511
        int r = idx >> 2;
        int c = (idx & 3) << 4;
        cp_async16_s(qbase + r * AT_ROWB + c,
                     qb + (size_t)(m0 + r) * D_ + c);
    }
    cp_commit();

    uint32_t a_off[4], b_off[2];
    #pragma unroll
    for (int mi = 0; mi < 4; mi++)
        a_off[mi] = qbase + (uint32_t)((wm*64 + mi*16 + (lane & 15)) * AT_ROWB + ((lane >> 4) * 16));
    #pragma unroll
    for (int p = 0; p < 2; p++)
        b_off[p] = kbase + (uint32_t)((wn*32 + p*16 + (lane & 15)) * AT_ROWB + ((lane >> 4) * 16));

    for (int tn = 0; tn < 4; tn++) {
        const int n0 = tn * 128;

        if (tn < tm) {     // fill-only tile: streaming NEG stores
            float4 negv = make_float4(NEG, NEG, NEG, NEG);
            #pragma unroll
            for (int it = 0; it < 16; it++) {
                int idx = tid + it * 256;      // 0..4095
                int r = idx >> 5;
                int c = (idx & 31) << 2;
                *reinterpret_cast<float4*>(&obase[(size_t)(m0 + r) * L_ + n0 + c]) = negv;
            }
            continue;
        }

        // protect kmem from previous iteration's reads, then load k tile
        __syncthreads();
        #pragma unroll
        for (int it = 0; it < 2; it++) {
            int idx = tid + it * 256;
            int r = idx >> 2;
            int c = (idx & 3) << 4;
            cp_async16_s(kbase + r * AT_ROWB + c,
                         kb + (size_t)(n0 + r) * D_ + c);
        }
        cp_commit();
        asm volatile("cp.async.wait_group 0;" ::: "memory");
        __syncthreads();

        float acc[4][4][4];
        #pragma unroll
        for (int mi = 0; mi < 4; mi++)
            #pragma unroll
            for (int nj = 0; nj < 4; nj++)
                #pragma unroll
                for (int x = 0; x < 4; x++)
                    acc[mi][nj][x] = 0.0f;

        #pragma unroll
        for (int ks = 0; ks < 2; ks++) {       // D=64 -> 2 k32 steps
            uint32_t koff = ks * 32;
            uint32_t a[4][4], bp[2][4];
            #pragma unroll
            for (int mi = 0; mi < 4; mi++)
                ldsm_x4(a[mi], a_off[mi] + koff);
            #pragma unroll
            for (int p = 0; p < 2; p++)
                ldsm_x4(bp[p], b_off[p] + koff);
            #pragma unroll
            for (int mi = 0; mi < 4; mi++)
                #pragma unroll
                for (int nj = 0; nj < 4; nj++) {
                    uint32_t bb[2] = { bp[nj >> 1][nj & 1], bp[nj >> 1][(nj & 1) + 2] };
                    mma16832(acc[mi][nj], a[mi], bb);
                }
        }

        // register epilogue: masked float2 stores
        #pragma unroll
        for (int mi = 0; mi < 4; mi++) {
            #pragma unroll
            for (int rh = 0; rh < 2; rh++) {
                int r_loc = wm*64 + mi*16 + (lane >> 2) + rh*8;
                int m = m0 + r_loc;
                bool rowok = (maskv[m] != 0);
                #pragma unroll
                for (int nj = 0; nj < 4; nj++) {
                    int n = n0 + wn*32 + nj*8 + (lane & 3) * 2;
                    float e0 = acc[mi][nj][rh*2 + 0] * 0.125f;
                    float e1 = acc[mi][nj][rh*2 + 1] * 0.125f;
                    bool v0 = rowok && maskv[n]     && (m <= n);
                    bool v1 = rowok && maskv[n + 1] && (m <= n + 1);
                    float2 val;
                    val.x = v0 ? e0 : NEG;
                    val.y = v1 ? e1 : NEG;
                    *reinterpret_cast<float2*>(&obase[(size_t)m * L_ + n]) = val;
                }
            }
        }
    }
}

// ---------------------------------------------------------------------------
extern "C" void kernel_launch(void* const* d_in, const int* in_sizes, int n_in,
                              void* d_out, int out_size) {
    const float* inputs = (const float*)d_in[0];
    const float* W      = (const float*)d_in[1];
    const float* bias   = (const float*)d_in[2];
    const int*   am     = (const int*)d_in[3];
    float* out = (float*)d_out;

    cudaFuncSetAttribute(gemm1_kernel, cudaFuncAttributeMaxDynamicSharedMemorySize, G1_SMEM);

    prep_kernel<<<(NAQ + NROPE + 255) / 256, 256>>>(inputs);
    wtrans_kernel<<<dim3(OUTD / 32, HID / 32), 256>>>(W);
    gemm1_kernel<<<dim3(H_, MROWS / 128), 256, G1_SMEM>>>(bias);
    attn_kernel<<<dim3(4, BHN), 256>>>(am, out);
}

// round 16
// speedup vs baseline: 1.1429x; 1.1429x over previous
#include <cuda_runtime.h>
#include <cuda_bf16.h>
#include <cuda_fp8.h>
#include <cstdint>

#define B_    8
#define L_    512
#define H_    12
#define D_    64
#define HID   768
#define OUTD  1536
#define MROWS 4096          // B_*L_
#define BHN   96            // B_*H_

#define NA4   (MROWS * HID / 4)     // 786432 float4 units of A
#define NAQ   (NA4 / 4)             // 196608
#define NROPE (L_ * 32)             //  16384

// Scratch (device globals — no runtime allocation allowed)
__device__ unsigned char g_a8[MROWS * HID];     // inputs e4m3 [4096 x 768]
__device__ unsigned char g_wt8[OUTD * HID];     // W^T e4m3 [1536 x 768] K-major
__device__ unsigned char g_q8[BHN * L_ * D_];   // q, (bh, l, d) e4m3
__device__ unsigned char g_k8[BHN * L_ * D_];   // k, (bh, l, d) e4m3
__device__ float         g_sin[NROPE];
__device__ float         g_cos[NROPE];

// All 16 128x128 tiles of the 512x512 logits: first 10 = upper (compute),
// last 6 = strictly-below-diagonal (fill-only).
__device__ const signed char T16_M[16] = {0,0,0,0,1,1,1,2,2,3, 1,2,2,3,3,3};
__device__ const signed char T16_N[16] = {0,1,2,3,1,2,3,2,3,3, 0,0,1,0,1,2};

// ---------------------------------------------------------------------------
// PTX helpers
// ---------------------------------------------------------------------------
static __device__ __forceinline__ uint32_t smem_u32(const void* p) {
    uint32_t a;
    asm("{ .reg .u64 t; cvta.to.shared.u64 t, %1; cvt.u32.u64 %0, t; }" : "=r"(a) : "l"(p));
    return a;
}
static __device__ __forceinline__ void cp_async16_s(uint32_t saddr, const void* g) {
    asm volatile("cp.async.cg.shared.global [%0], [%1], 16;\n" :: "r"(saddr), "l"(g));
}
static __device__ __forceinline__ void cp_commit() {
    asm volatile("cp.async.commit_group;\n" ::: "memory");
}
static __device__ __forceinline__ void ldsm_x4(uint32_t* r, uint32_t addr) {
    asm volatile("ldmatrix.sync.aligned.m8n8.x4.shared.b16 {%0,%1,%2,%3}, [%4];"
                 : "=r"(r[0]), "=r"(r[1]), "=r"(r[2]), "=r"(r[3]) : "r"(addr));
}
// fp8 e4m3 MMA: D(16x8 f32) += A(16x32) * B(8x32)^T
static __device__ __forceinline__ void mma16832(float* d, const uint32_t* a, const uint32_t* b) {
    asm volatile(
        "mma.sync.aligned.m16n8k32.row.col.f32.e4m3.e4m3.f32 "
        "{%0,%1,%2,%3}, {%4,%5,%6,%7}, {%8,%9}, {%0,%1,%2,%3};"
        : "+f"(d[0]), "+f"(d[1]), "+f"(d[2]), "+f"(d[3])
        : "r"(a[0]), "r"(a[1]), "r"(a[2]), "r"(a[3]), "r"(b[0]), "r"(b[1]));
}
static __device__ __forceinline__ unsigned short f2_to_e4m3x2(float x, float y) {
    return (unsigned short)__nv_cvt_float2_to_fp8x2(make_float2(x, y), __NV_SATFINITE, __NV_E4M3);
}

// ---------------------------------------------------------------------------
// Kernel 0: convert inputs to e4m3 + RoPE tables.
// ---------------------------------------------------------------------------
static __device__ __forceinline__ void conv_a(const float* __restrict__ A, int j) {
    float4 v = reinterpret_cast<const float4*>(A)[j];
    uint32_t lo = f2_to_e4m3x2(v.x, v.y);
    uint32_t hi = f2_to_e4m3x2(v.z, v.w);
    reinterpret_cast<uint32_t*>(g_a8)[j] = lo | (hi << 16);
}

__global__ __launch_bounds__(256) void prep_kernel(const float* __restrict__ A) {
    int idx = blockIdx.x * 256 + threadIdx.x;
    if (idx < NAQ) {
        conv_a(A, idx);
        conv_a(A, idx + NAQ);
        conv_a(A, idx + 2 * NAQ);
        conv_a(A, idx + 3 * NAQ);
    } else if (idx < NAQ + NROPE) {
        int t = idx - NAQ;
        int l = t >> 5;
        int i = t & 31;
        float invf = exp2f((float)i * -0.41524101186092027f);
        float s, c;
        sincosf((float)l * invf, &s, &c);
        g_sin[t] = s;
        g_cos[t] = c;
    }
}

// ---------------------------------------------------------------------------
// Kernel 0b: W [768 x 1536] f32 -> g_wt8 [1536 x 768] e4m3 (tiled transpose)
// ---------------------------------------------------------------------------
__global__ __launch_bounds__(256) void wtrans_kernel(const float* __restrict__ W) {
    __shared__ float t[32][33];
    int n0 = blockIdx.x * 32, k0 = blockIdx.y * 32;
    int tx = threadIdx.x & 31, ty = threadIdx.x >> 5;   // 32x8
    #pragma unroll
    for (int i = 0; i < 4; i++)
        t[ty + i*8][tx] = W[(size_t)(k0 + ty + i*8) * OUTD + n0 + tx];
    __syncthreads();
    #pragma unroll
    for (int i = 0; i < 4; i++)
        g_wt8[(size_t)(n0 + ty + i*8) * HID + k0 + tx] =
            (unsigned char)__nv_cvt_float_to_fp8(t[tx][ty + i*8], __NV_SATFINITE, __NV_E4M3);
}

// ---------------------------------------------------------------------------
// Kernel 1: x = inputs @ W via fp8 mma.sync, bias+RoPE in registers, e4m3 out.
// Block 128m x 128n (one head), 8 warps (2x4), warp 64m x 32n.
// BK=128, 2-stage cp.async pipeline. Output staged in smem -> STG.128.
// ---------------------------------------------------------------------------
#define G1_ROWB   144                       // 128B fp8 data + 16B pad
#define G1_OPB    (128 * G1_ROWB)           // 18432 per operand
#define G1_STAGE  (2 * G1_OPB)              // 36864
#define G1_SMEM   (2 * G1_STAGE)            // 73728
#define ST_ROWB   144                       // staging row stride (conflict-free)

__global__ __launch_bounds__(256, 2) void gemm1_kernel(const float* __restrict__ bias) {
    extern __shared__ __align__(16) unsigned char dsm[];
    __shared__ float bias_s[128];

    const int tid  = threadIdx.x;
    const int lane = tid & 31;
    const int w    = tid >> 5;
    const int wm   = w >> 2;             // 0..1 (m offset 64)
    const int wn   = w & 3;              // 0..3 (n offset 32)
    const int h    = blockIdx.x;
    const int m0   = blockIdx.y * 128;
    const int n0   = h * 128;

    if (tid < 128) bias_s[tid] = __ldg(&bias[n0 + tid]);

    const uint32_t sbase = smem_u32(dsm);

    auto copy_stage = [&](int kt) {
        uint32_t base = sbase + (kt & 1) * G1_STAGE;
        int k0e = kt * 128;
        #pragma unroll
        for (int it = 0; it < 8; it++) {
            int idx = tid + it * 256;            // 0..2047
            int r = (idx >> 3) & 127;
            int c = idx & 7;                     // 16B chunk
            if (idx < 1024)
                cp_async16_s(base + r * G1_ROWB + c * 16,
                             &g_a8[(size_t)(m0 + r) * HID + k0e + c * 16]);
            else
                cp_async16_s(base + G1_OPB + r * G1_ROWB + c * 16,
                             &g_wt8[(size_t)(n0 + r) * HID + k0e + c * 16]);
        }
    };

    uint32_t a_off[4], b_off[2];
    #pragma unroll
    for (int mi = 0; mi < 4; mi++)
        a_off[mi] = (uint32_t)((wm*64 + mi*16 + (lane & 15)) * G1_ROWB + ((lane >> 4) * 16));
    #pragma unroll
    for (int p = 0; p < 2; p++)
        b_off[p] = (uint32_t)(G1_OPB + (wn*32 + p*16 + (lane & 15)) * G1_ROWB + ((lane >> 4) * 16));

    float acc[4][4][4];
    #pragma unroll
    for (int mi = 0; mi < 4; mi++)
        #pragma unroll
        for (int nj = 0; nj < 4; nj++)
            #pragma unroll
            for (int x = 0; x < 4; x++)
                acc[mi][nj][x] = 0.0f;

    copy_stage(0); cp_commit();

    const int NT = HID / 128;   // 6
    for (int kt = 0; kt < NT; kt++) {
        if (kt + 1 < NT) {
            copy_stage(kt + 1); cp_commit();
            asm volatile("cp.async.wait_group 1;" ::: "memory");
        } else {
            asm volatile("cp.async.wait_group 0;" ::: "memory");
        }
        __syncthreads();

        uint32_t stg = sbase + (kt & 1) * G1_STAGE;
        #pragma unroll
        for (int ks = 0; ks < 4; ks++) {         // four k32 steps per BK=128
            uint32_t koff = ks * 32;
            uint32_t a[4][4], bp[2][4];
            #pragma unroll
            for (int mi = 0; mi < 4; mi++)
                ldsm_x4(a[mi], stg + a_off[mi] + koff);
            #pragma unroll
            for (int p = 0; p < 2; p++)
                ldsm_x4(bp[p], stg + b_off[p] + koff);
            #pragma unroll
            for (int mi = 0; mi < 4; mi++)
                #pragma unroll
                for (int nj = 0; nj < 4; nj++) {
                    uint32_t bb[2] = { bp[nj >> 1][nj & 1], bp[nj >> 1][(nj & 1) + 2] };
                    mma16832(acc[mi][nj], a[mi], bb);
                }
        }
        __syncthreads();
    }

    // Epilogue: bias + RoPE in registers -> fp8x2 into smem staging
    // (row stride 144B => conflict-free STS.16), then coalesced STG.128.
    unsigned char* stage = dsm;             // 128 x 144 = 18432 bytes
    float bv[4][2];
    #pragma unroll
    for (int nj = 0; nj < 4; nj++) {
        int nl = wn*32 + nj*8 + (lane & 3) * 2;
        bv[nj][0] = bias_s[nl];
        bv[nj][1] = bias_s[nl + 1];
    }

    #pragma unroll
    for (int mi = 0; mi < 4; mi++) {
        #pragma unroll
        for (int rh = 0; rh < 2; rh++) {
            int row = wm*64 + mi*16 + (lane >> 2) + rh*8;    // 0..127
            int l = (m0 + row) & (L_ - 1);
            #pragma unroll
            for (int nj = 0; nj < 4; nj++) {
                float x1 = acc[mi][nj][rh*2 + 0] + bv[nj][0];
                float x2 = acc[mi][nj][rh*2 + 1] + bv[nj][1];
                int nl = wn*32 + nj*8 + (lane & 3) * 2;
                int i  = (nl & 63) >> 1;
                float s = g_sin[l * 32 + i];
                float c = g_cos[l * 32 + i];
                unsigned short pr = f2_to_e4m3x2(x1 * c - x2 * s, x1 * s + x2 * c);
                *reinterpret_cast<unsigned short*>(stage + row * ST_ROWB + nl) = pr;
            }
        }
    }
    __syncthreads();

    // 128 rows x 8 chunks of 16B = 1024 uint4; 4 per thread.
    #pragma unroll
    for (int it = 0; it < 4; it++) {
        int idx = tid + it * 256;           // 0..1023
        int row = idx >> 3;
        int c   = idx & 7;
        uint4 v = *reinterpret_cast<const uint4*>(stage + row * ST_ROWB + c * 16);
        int m_g = m0 + row;
        int l = m_g & (L_ - 1);
        int bidx = m_g >> 9;
        unsigned char* dst = (c < 4) ? g_q8 : g_k8;
        int d = (c & 3) * 16;
        *reinterpret_cast<uint4*>(&dst[((size_t)(bidx * H_ + h) * L_ + l) * D_ + d]) = v;
    }
}

// ---------------------------------------------------------------------------
// Kernel 2: logits = (q @ k^T)/8 over ALL 16 tiles; below-diagonal tiles take
// a store-only fast path. fp8 mma.sync, 8 warps (2x4), warp 64m x 32n.
// Epilogue: Es-staged coalesced float4 stores with mask-specialized paths:
//   allok && tm<tn : scale+store only (no compares)
//   allok && tm==tn: causal compare only
//   else           : full row/col/causal masking
// ---------------------------------------------------------------------------
#define AT_ROWB 80    // 64 fp8 (64B) + 16B pad

__global__ __launch_bounds__(256, 2) void attn_kernel(const int* __restrict__ am,
                                                      float* __restrict__ out) {
    const int bh = blockIdx.y;
    const int tm = (int)T16_M[blockIdx.x];
    const int tn = (int)T16_N[blockIdx.x];
    const int m0 = tm * 128, n0 = tn * 128;
    float* obase = out + (size_t)bh * L_ * L_;
    const float NEG = __int_as_float(0xFF7FFFFF);  // -FLT_MAX == finfo(f32).min
    const int tid  = threadIdx.x;

    if (tm > tn) {   // fill-only tile
        float4 negv = make_float4(NEG, NEG, NEG, NEG);
        #pragma unroll
        for (int it = 0; it < 16; it++) {
            int idx = tid + it * 256;          // 0..4095
            int r = idx >> 5;
            int c = (idx & 31) << 2;
            *reinterpret_cast<float4*>(&obase[(size_t)(m0 + r) * L_ + n0 + c]) = negv;
        }
        return;
    }

    const int b    = bh / H_;
    const int lane = tid & 31;
    const int w    = tid >> 5;
    const int wm   = w >> 2;     // 0..1
    const int wn   = w & 3;      // 0..3

    // union: q/k tiles (2 x 10240 = 20480) then reused as Es 64x132 f32 (33792)
    __shared__ __align__(16) unsigned char smem_raw[64 * 132 * 4];
    __shared__ unsigned char rowv[128];
    __shared__ unsigned char colv[128];
    unsigned char* qmem = smem_raw;
    unsigned char* kmem = smem_raw + 128 * AT_ROWB;
    float (*Es)[132] = reinterpret_cast<float (*)[132]>(smem_raw);

    const int* amb = am + b * L_;
    int myok;
    if (tid < 128) { myok = (amb[m0 + tid] != 0);       rowv[tid]       = (unsigned char)myok; }
    else           { myok = (amb[n0 + tid - 128] != 0); colv[tid - 128] = (unsigned char)myok; }
    const int allok = __syncthreads_and(myok);

    const unsigned char* qb = &g_q8[(size_t)bh * L_ * D_];
    const unsigned char* kb = &g_k8[(size_t)bh * L_ * D_];

    // 128 rows x 64B per row = 512 uint4 per matrix; 2 per thread each
    #pragma unroll
    for (int it = 0; it < 2; it++) {
        int idx = tid + it * 256;              // 0..511
        int r = idx >> 2;
        int c = (idx & 3) << 4;                // byte offset within row
        *reinterpret_cast<uint4*>(qmem + r * AT_ROWB + c) =
            *reinterpret_cast<const uint4*>(qb + (size_t)(m0 + r) * D_ + c);
        *reinterpret_cast<uint4*>(kmem + r * AT_ROWB + c) =
            *reinterpret_cast<const uint4*>(kb + (size_t)(n0 + r) * D_ + c);
    }
    __syncthreads();

    const uint32_t qbase = smem_u32(qmem);
    const uint32_t kbase = smem_u32(kmem);

    uint32_t a_off[4], b_off[2];
    #pragma unroll
    for (int mi = 0; mi < 4; mi++)
        a_off[mi] = qbase + (uint32_t)((wm*64 + mi*16 + (lane & 15)) * AT_ROWB + ((lane >> 4) * 16));
    #pragma unroll
    for (int p = 0; p < 2; p++)
        b_off[p] = kbase + (uint32_t)((wn*32 + p*16 + (lane & 15)) * AT_ROWB + ((lane >> 4) * 16));

    float acc[4][4][4];
    #pragma unroll
    for (int mi = 0; mi < 4; mi++)
        #pragma unroll
        for (int nj = 0; nj < 4; nj++)
            #pragma unroll
            for (int x = 0; x < 4; x++)
                acc[mi][nj][x] = 0.0f;

    #pragma unroll
    for (int ks = 0; ks < 2; ks++) {           // D=64 -> 2 k32 steps
        uint32_t koff = ks * 32;
        uint32_t a[4][4], bp[2][4];
        #pragma unroll
        for (int mi = 0; mi < 4; mi++)
            ldsm_x4(a[mi], a_off[mi] + koff);
        #pragma unroll
        for (int p = 0; p < 2; p++)
            ldsm_x4(bp[p], b_off[p] + koff);
        #pragma unroll
        for (int mi = 0; mi < 4; mi++)
            #pragma unroll
            for (int nj = 0; nj < 4; nj++) {
                uint32_t bb[2] = { bp[nj >> 1][nj & 1], bp[nj >> 1][(nj & 1) + 2] };
                mma16832(acc[mi][nj], a[mi], bb);
            }
    }

    // Two 64-row passes: warps with wm==half stage their acc to Es, then all
    // 256 threads do masked coalesced float4 stores via the specialized paths.
    #pragma unroll
    for (int half = 0; half < 2; half++) {
        __syncthreads();
        if (wm == half) {
            #pragma unroll
            for (int mi = 0; mi < 4; mi++)
                #pragma unroll
                for (int rh = 0; rh < 2; rh++) {
                    int row = mi*16 + (lane >> 2) + rh*8;   // 0..63
                    #pragma unroll
                    for (int nj = 0; nj < 4; nj++) {
                        int col = wn*32 + nj*8 + (lane & 3)*2;
                        float2 v2 = make_float2(acc[mi][nj][rh*2 + 0],
                                                acc[mi][nj][rh*2 + 1]);
                        *reinterpret_cast<float2*>(&Es[row][col]) = v2;
                    }
                }
        }
        __syncthreads();

        // 64 rows x 32 float4 = 2048 / 256 = 8 iterations
        if (allok && tm < tn) {
            // no masking at all
            #pragma unroll
            for (int it = 0; it < 8; it++) {
                int f = tid + it * 256;
                int r = f >> 5;
                int c4 = (f & 31) << 2;
                int m = m0 + half * 64 + r;
                float4 v;
                v.x = Es[r][c4+0] * 0.125f;
                v.y = Es[r][c4+1] * 0.125f;
                v.z = Es[r][c4+2] * 0.125f;
                v.w = Es[r][c4+3] * 0.125f;
                *reinterpret_cast<float4*>(&obase[(size_t)m * L_ + n0 + c4]) = v;
            }
        } else if (allok) {
            // diagonal tile: causal compare only
            #pragma unroll
            for (int it = 0; it < 8; it++) {
                int f = tid + it * 256;
                int r = f >> 5;
                int c4 = (f & 31) << 2;
                int m = m0 + half * 64 + r;
                int n = n0 + c4;
                float4 v;
                v.x = (m <= n+0) ? Es[r][c4+0] * 0.125f : NEG;
                v.y = (m <= n+1) ? Es[r][c4+1] * 0.125f : NEG;
                v.z = (m <= n+2) ? Es[r][c4+2] * 0.125f : NEG;
                v.w = (m <= n+3) ? Es[r][c4+3] * 0.125f : NEG;
                *reinterpret_cast<float4*>(&obase[(size_t)m * L_ + n]) = v;
            }
        } else {
            // general masking
            #pragma unroll
            for (int it = 0; it < 8; it++) {
                int f = tid + it * 256;
                int r = f >> 5;
                int c4 = (f & 31) << 2;
                int m = m0 + half * 64 + r;
                int n = n0 + c4;
                bool rowok = (rowv[half * 64 + r] != 0);
                uchar4 cv = *reinterpret_cast<const uchar4*>(&colv[c4]);
                float4 v;
                v.x = (rowok && cv.x && (m <= n+0)) ? Es[r][c4+0] * 0.125f : NEG;
                v.y = (rowok && cv.y && (m <= n+1)) ? Es[r][c4+1] * 0.125f : NEG;
                v.z = (rowok && cv.z && (m <= n+2)) ? Es[r][c4+2] * 0.125f : NEG;
                v.w = (rowok && cv.w && (m <= n+3)) ? Es[r][c4+3] * 0.125f : NEG;
                *reinterpret_cast<float4*>(&obase[(size_t)m * L_ + n]) = v;
            }
        }
    }
}

// ---------------------------------------------------------------------------
extern "C" void kernel_launch(void* const* d_in, const int* in_sizes, int n_in,
                              void* d_out, int out_size) {
    const float* inputs = (const float*)d_in[0];
    const float* W      = (const float*)d_in[1];
    const float* bias   = (const float*)d_in[2];
    const int*   am     = (const int*)d_in[3];
    float* out = (float*)d_out;

    cudaFuncSetAttribute(gemm1_kernel, cudaFuncAttributeMaxDynamicSharedMemorySize, G1_SMEM);

    prep_kernel<<<(NAQ + NROPE + 255) / 256, 256>>>(inputs);
    wtrans_kernel<<<dim3(OUTD / 32, HID / 32), 256>>>(W);
    gemm1_kernel<<<dim3(H_, MROWS / 128), 256, G1_SMEM>>>(bias);
    attn_kernel<<<dim3(16, BHN), 256>>>(am, out);
}